// round 17
// baseline (speedup 1.0000x reference)
#include <cuda_runtime.h>
#include <cstdint>

#define BATCHES 8
#define NB      32768
#define NCLS    81
#define PRE_K   2048
#define FKTGT   256
#define FCAP    1024
#define FLCAP   4096
#define CAP     4096
#define MAX_OUT 200
#define SB_ANCH 128
#define NTILES  4
#define TILE_ELEMS (SB_ANCH * NCLS)
#define NBINS   9024
#define WALKCH  (NBINS / 32)
#define BINBASE 0x3D4CCu
#define NFINE   96
#define MROWS   384
#define MWORDS  12
#define FUSED_DYN 69632
#define SCORE_DYN (2 * TILE_ELEMS * 4)

// ---------------- scratch (device globals) ---------------------------------
__device__ unsigned long long g_keys[BATCHES * NB];
__device__ unsigned char      g_cat [BATCHES * NB];
__device__ unsigned int      g_hist[BATCHES * NBINS];
__device__ unsigned int      g_fhist[BATCHES * NFINE];
__device__ unsigned int      g_flcnt[BATCHES];
__device__ unsigned long long g_flist[BATCHES * FLCAP];

// ---------------- kernel 1: score/argmax + hists + bootstrap fastlist ------
__global__ void __launch_bounds__(SB_ANCH)
score_kernel(const float* __restrict__ confs) {
    extern __shared__ float sbuf[];
    __shared__ alignas(8) unsigned long long mbar[2];

    const unsigned bytes = TILE_ELEMS * 4;
    unsigned mb0 = (unsigned)__cvta_generic_to_shared(&mbar[0]);
    unsigned mb1 = (unsigned)__cvta_generic_to_shared(&mbar[1]);
    unsigned sb0 = (unsigned)__cvta_generic_to_shared(sbuf);
    unsigned sb1 = (unsigned)__cvta_generic_to_shared(sbuf + TILE_ELEMS);
    const int tile0 = blockIdx.x * NTILES;
    const unsigned T0b = __float_as_uint(0.999f);
    const int lane = threadIdx.x & 31;

    if (threadIdx.x == 0) {
        asm volatile("mbarrier.init.shared.b64 [%0], 1;" :: "r"(mb0) : "memory");
        asm volatile("mbarrier.init.shared.b64 [%0], 1;" :: "r"(mb1) : "memory");
    }
    __syncthreads();
    if (threadIdx.x == 0) {
        asm volatile("mbarrier.arrive.expect_tx.shared.b64 _, [%0], %1;"
                     :: "r"(mb0), "r"(bytes) : "memory");
        asm volatile("cp.async.bulk.shared::cta.global.mbarrier::complete_tx::bytes [%0], [%1], %2, [%3];"
                     :: "r"(sb0), "l"(confs + (size_t)(tile0 + 0) * TILE_ELEMS),
                        "r"(bytes), "r"(mb0) : "memory");
        asm volatile("mbarrier.arrive.expect_tx.shared.b64 _, [%0], %1;"
                     :: "r"(mb1), "r"(bytes) : "memory");
        asm volatile("cp.async.bulk.shared::cta.global.mbarrier::complete_tx::bytes [%0], [%1], %2, [%3];"
                     :: "r"(sb1), "l"(confs + (size_t)(tile0 + 1) * TILE_ELEMS),
                        "r"(bytes), "r"(mb1) : "memory");
    }

    #pragma unroll
    for (int t = 0; t < NTILES; t++) {
        const unsigned mba = (t & 1) ? mb1 : mb0;
        const unsigned par = (unsigned)((t >> 1) & 1);
        unsigned done = 0;
        do {
            asm volatile("{\n\t.reg .pred P;\n\t"
                         "mbarrier.try_wait.parity.acquire.cta.shared::cta.b64 P, [%1], %2, 0x989680;\n\t"
                         "selp.b32 %0, 1, 0, P;\n\t}"
                         : "=r"(done) : "r"(mba), "r"(par) : "memory");
        } while (!done);

        const float* row = sbuf + (t & 1) * TILE_ELEMS + threadIdx.x * NCLS;
        float m = -1.0f; int mi = 0;
        #pragma unroll
        for (int j = 0; j < NCLS; j++) {
            float v = row[j];
            if (v > m) { m = v; mi = j; }
        }
        const int a = (tile0 + t) * SB_ANCH + threadIdx.x;
        const int b = a >> 15;
        bool valid = (m > 0.05f) && (mi != 0);
        unsigned int n = (unsigned int)a & (NB - 1);
        unsigned long long key = 0ULL;
        unsigned int sbv = 0;
        if (valid) {
            sbv = __float_as_uint(m);
            key = (((unsigned long long)sbv) << 32) | (unsigned long long)(NB - 1u - n);
            unsigned int bucket = (sbv >> 12) - BINBASE;
            atomicAdd(&g_hist[b * NBINS + bucket], 1u);
        }
        g_keys[a] = key;
        g_cat[a]  = (unsigned char)mi;

        bool hot = valid && (sbv >= T0b);
        if (hot) atomicAdd(&g_fhist[b * NFINE + ((sbv - T0b) >> 8)], 1u);
        unsigned bal = __ballot_sync(0xffffffffu, hot);
        if (bal) {
            int leader = __ffs(bal) - 1;
            unsigned basep = 0;
            if (lane == leader) basep = atomicAdd(&g_flcnt[b], (unsigned)__popc(bal));
            basep = __shfl_sync(0xffffffffu, basep, leader);
            if (hot) {
                unsigned pos = basep + (unsigned)__popc(bal & ((1u << lane) - 1u));
                if (pos < FLCAP) g_flist[(size_t)b * FLCAP + pos] = key;
            }
        }

        __syncthreads();
        if (t + 2 < NTILES && threadIdx.x == 0) {
            const unsigned dsb = (t & 1) ? sb1 : sb0;
            asm volatile("mbarrier.arrive.expect_tx.shared.b64 _, [%0], %1;"
                         :: "r"(mba), "r"(bytes) : "memory");
            asm volatile("cp.async.bulk.shared::cta.global.mbarrier::complete_tx::bytes [%0], [%1], %2, [%3];"
                         :: "r"(dsb), "l"(confs + (size_t)(tile0 + t + 2) * TILE_ELEMS),
                            "r"(bytes), "r"(mba) : "memory");
        }
    }
}

// ---------------- full-path NMS (warp-serial; slow path only) --------------
__device__ __forceinline__ int run_nms_warp(const float4* scand, const short* scls,
                                            short* kept_idx, int lim, int lane) {
    float kx1[7], ky1[7], kx2[7], ky2[7], kar[7];
    short kcl[7];
    int nk = 0;
    for (int i = 0; i < lim && nk < MAX_OUT; i++) {
        short ci = scls[i];
        if (ci < 0) break;
        float4 bb = scand[i];
        float ar = fmaxf(bb.z - bb.x, 0.f) * fmaxf(bb.w - bb.y, 0.f);
        bool sup = false;
        const int ns = (nk + 31) >> 5;
        #pragma unroll
        for (int s = 0; s < 7; s++) {
            if (s >= ns) break;
            if ((s * 32 + lane) < nk && kcl[s] == ci) {
                float ix1 = fmaxf(bb.x, kx1[s]);
                float iy1 = fmaxf(bb.y, ky1[s]);
                float ix2 = fminf(bb.z, kx2[s]);
                float iy2 = fminf(bb.w, ky2[s]);
                float inter = fmaxf(ix2 - ix1, 0.f) * fmaxf(iy2 - iy1, 0.f);
                float uni   = ar + kar[s] - inter;
                if (inter / fmaxf(uni, 1e-9f) > 0.5f) sup = true;
            }
        }
        sup = __any_sync(0xffffffffu, sup);
        if (!sup) {
            int slot = nk >> 5;
            if ((nk & 31) == lane) {
                #pragma unroll
                for (int s = 0; s < 7; s++) {
                    if (slot == s) {
                        kx1[s] = bb.x; ky1[s] = bb.y;
                        kx2[s] = bb.z; ky2[s] = bb.w;
                        kar[s] = ar;   kcl[s] = ci;
                    }
                }
            }
            if (lane == 0) kept_idx[nk] = (short)i;
            nk++;
        }
    }
    return nk;
}

// ---------------- kernel 2: FUSED everything (lazy coarse walk) ------------
__global__ void __launch_bounds__(1024)
fused_kernel(const float* __restrict__ boxes, float* __restrict__ out, int write_cats) {
    extern __shared__ unsigned char dyn[];
    unsigned int*       fcand32 = (unsigned int*)dyn;
    unsigned long long* fcand = (unsigned long long*)dyn;
    float4*             scand = (float4*)(dyn + 8192);
    unsigned char*      cls8  = (unsigned char*)(dyn + 24576);
    unsigned int*       M     = (unsigned int*)(dyn + 25600);
    unsigned long long* cand   = (unsigned long long*)dyn;
    float4*             scand2 = (float4*)(dyn + 32768);
    short*              scls2  = (short*)(dyn + 65536);

    __shared__ unsigned int s_Tb, s_Tbf, s_scnt, s_fcnt, s_fc, s_cnt2, s_flcnt;
    __shared__ unsigned int s_tfF, s_fcntF, s_haveF;
    __shared__ unsigned short clist[MROWS];
    __shared__ unsigned short coff[NCLS + 1];
    __shared__ unsigned int   cpos[NCLS];
    __shared__ short  kept_idx[MAX_OUT];
    __shared__ int    sh_nk;

    const int b = blockIdx.x;
    const int tid  = threadIdx.x;
    const int lane = tid & 31;
    const int warp = tid >> 5;
    const unsigned T0b = __float_as_uint(0.999f);

    if (tid == 0) {
        s_fc = 0; s_haveF = 0;
        s_flcnt = g_flcnt[b];
        g_flcnt[b] = 0;
    }

    unsigned int* gfh = g_fhist + (size_t)b * NFINE;
    unsigned int* gh  = g_hist  + (size_t)b * NBINS;

    // ---- A1: warp-0 fine-hist walk, prefetched loads ----
    if (warp == 0) {
        unsigned v0 = gfh[95 - lane];      // chunk 0: bins 95..64
        unsigned v1 = gfh[63 - lane];      // chunk 1
        unsigned v2 = gfh[31 - lane];      // chunk 2
        unsigned run = 0; int found = 0;
        unsigned tf = 0, fcv = 0;
        unsigned vs[3] = {v0, v1, v2};
        #pragma unroll
        for (int c = 0; c < 3; c++) {
            unsigned v = vs[c];
            int bin = NFINE - 1 - c * 32 - lane;
            unsigned p = v;
            #pragma unroll
            for (int off = 1; off < 32; off <<= 1) {
                unsigned t = __shfl_up_sync(0xffffffffu, p, off);
                if (lane >= off) p += t;
            }
            unsigned cum = run + p;
            if (!found) {
                unsigned cr = __ballot_sync(0xffffffffu, cum >= FKTGT && cum - v < FKTGT);
                if (cr) {
                    int src = __ffs(cr) - 1;
                    tf  = __shfl_sync(0xffffffffu, (unsigned)bin, src);
                    fcv = __shfl_sync(0xffffffffu, cum, src);
                    found = 1;
                }
            }
            run = __shfl_sync(0xffffffffu, cum, 31);
        }
        if (lane == 0) { s_tfF = tf; s_fcntF = fcv; s_haveF = (unsigned)found; }
    }
    __syncthreads();
    if (tid < NFINE) gfh[tid] = 0u;        // zero fine hist (after reads)

    const unsigned int flcnt = s_flcnt;
    const bool fine_ok = (s_haveF != 0) && (flcnt <= FLCAP) && (s_fcntF <= FCAP);
    const unsigned long long* keys = g_keys + (size_t)b * NB;
    const float*         bxs  = boxes + (size_t)b * NB * 4;
    const unsigned char* cats = g_cat + (size_t)b * NB;
    float* out5 = out + (size_t)b * MAX_OUT * 5;
    float* ocat = out + (size_t)BATCHES * MAX_OUT * 5 + (size_t)b * MAX_OUT;

    unsigned int cnt = 0;
    int nk_fast = -1;

    if (fine_ok) {
        // ================= FINE FAST PATH (u32 keys from flist) =============
        const unsigned TfF = T0b + (s_tfF << 8);
        const unsigned long long* fl = g_flist + (size_t)b * FLCAP;
        #pragma unroll
        for (int it = 0; it < 4; it++) {
            int i = it * 1024 + tid;
            unsigned long long k = (i < (int)flcnt) ? fl[i] : 0ULL;
            unsigned sb = (unsigned)(k >> 32);
            bool cf = (sb >= TfF) && (k != 0ULL);
            unsigned balf = __ballot_sync(0xffffffffu, cf);
            if (balf) {
                int leader = __ffs(balf) - 1;
                unsigned int basep = 0;
                if (lane == leader) basep = atomicAdd(&s_fc, (unsigned)__popc(balf));
                basep = __shfl_sync(0xffffffffu, basep, leader);
                if (cf) {
                    unsigned int pos = basep + (unsigned)__popc(balf & ((1u << lane) - 1u));
                    if (pos < FCAP)
                        fcand32[pos] = ((sb - T0b + 1u) << 15) | ((unsigned)k & 0x7FFFu);
                }
            }
        }
        __syncthreads();
        cnt = s_fc; if (cnt > FCAP) cnt = FCAP;

        int nsort = 64;
        while (nsort < (int)cnt) nsort <<= 1;
        if (tid < nsort && tid >= (int)cnt) fcand32[tid] = 0u;
        __syncthreads();

        if (tid < nsort) {
            unsigned v = fcand32[tid];
            #pragma unroll
            for (int k = 2; k <= 32; k <<= 1) {
                #pragma unroll
                for (int j = k >> 1; j >= 1; j >>= 1) {
                    unsigned o = __shfl_xor_sync(0xffffffffu, v, j);
                    bool up    = ((tid & k) == 0);
                    bool lower = ((tid & j) == 0);
                    unsigned mx = v > o ? v : o;
                    unsigned mn = v > o ? o : v;
                    v = (up == lower) ? mx : mn;
                }
            }
            fcand32[tid] = v;
        }
        __syncthreads();
        for (int k = 64; k <= nsort; k <<= 1) {
            for (int j = k >> 1; j >= 32; j >>= 1) {
                if (tid < nsort) {
                    int l = tid ^ j;
                    if (l > tid) {
                        unsigned a = fcand32[tid], bb = fcand32[l];
                        bool up = ((tid & k) == 0);
                        if ((a < bb) == up) { fcand32[tid] = bb; fcand32[l] = a; }
                    }
                }
                __syncthreads();
            }
            if (tid < nsort) {
                unsigned v = fcand32[tid];
                #pragma unroll
                for (int j = 16; j >= 1; j >>= 1) {
                    unsigned o = __shfl_xor_sync(0xffffffffu, v, j);
                    bool up    = ((tid & k) == 0);
                    bool lower = ((tid & j) == 0);
                    unsigned mx = v > o ? v : o;
                    unsigned mn = v > o ? o : v;
                    v = (up == lower) ? mx : mn;
                }
                fcand32[tid] = v;
            }
            __syncthreads();
        }
        // expand u32 -> u64 in place
        unsigned v32 = (tid < (int)cnt) ? fcand32[tid] : 0u;
        __syncthreads();
        fcand[tid] = v32
            ? ((((unsigned long long)((v32 >> 15) - 1u + T0b)) << 32)
               | (unsigned long long)(v32 & 0x7FFFu))
            : 0ULL;
        __syncthreads();

        // ---- stage boxes/classes; zero matrix; class lists ----
        {
            unsigned long long k = (tid < (int)cnt) ? fcand[tid] : 0ULL;
            if (k == 0ULL) {
                cls8[tid] = 0xFF;
                scand[tid] = make_float4(0.f, 0.f, 0.f, 0.f);
            } else {
                int idx = (NB - 1) - (int)(unsigned int)k;
                scand[tid] = *(const float4*)(bxs + (size_t)idx * 4);
                cls8[tid]  = cats[idx];
            }
        }
        #pragma unroll
        for (int u = tid; u < MROWS * MWORDS; u += 1024) M[u] = 0u;
        if (tid < NCLS) cpos[tid] = 0u;
        __syncthreads();

        const int lim = ((int)cnt < MROWS) ? (int)cnt : MROWS;

        if (tid < lim) atomicAdd(&cpos[cls8[tid]], 1u);
        __syncthreads();
        if (warp == 0) {
            unsigned carry = 0;
            if (lane == 0) coff[0] = 0;
            #pragma unroll
            for (int c0 = 0; c0 < NCLS; c0 += 32) {
                int idx = c0 + lane;
                unsigned v = (idx < NCLS) ? cpos[idx] : 0u;
                unsigned p = v;
                #pragma unroll
                for (int off = 1; off < 32; off <<= 1) {
                    unsigned t = __shfl_up_sync(0xffffffffu, p, off);
                    if (lane >= off) p += t;
                }
                if (idx < NCLS) coff[idx + 1] = (unsigned short)(carry + p);
                carry += __shfl_sync(0xffffffffu, p, 31);
            }
        }
        __syncthreads();
        if (tid < NCLS) cpos[tid] = coff[tid];
        __syncthreads();
        if (tid < lim) {
            unsigned p = atomicAdd(&cpos[cls8[tid]], 1u);
            clist[p] = (unsigned short)tid;
        }
        __syncthreads();

        if (tid < lim) {
            const int r = tid;
            const int c = cls8[r];
            float4 br = scand[r];
            float arr = fmaxf(br.z - br.x, 0.f) * fmaxf(br.w - br.y, 0.f);
            const int e0 = coff[c], e1 = coff[c + 1];
            for (int e = e0; e < e1; e++) {
                int j = clist[e];
                if (j == r) continue;
                float4 bj = scand[j];
                float ix1 = fmaxf(br.x, bj.x);
                float iy1 = fmaxf(br.y, bj.y);
                float ix2 = fminf(br.z, bj.z);
                float iy2 = fminf(br.w, bj.w);
                float inter = fmaxf(ix2 - ix1, 0.f) * fmaxf(iy2 - iy1, 0.f);
                float aj = fmaxf(bj.z - bj.x, 0.f) * fmaxf(bj.w - bj.y, 0.f);
                float uni = arr + aj - inter;
                if (inter / fmaxf(uni, 1e-9f) > 0.5f)
                    atomicOr(&M[r * MWORDS + (j >> 5)], 1u << (j & 31));
            }
        }
        __syncthreads();

        if (tid < 32) {
            unsigned sup = 0;
            int nk = 0;
            const int nwords = (lim + 31) >> 5;
            for (int w = 0; w < nwords; w++) {
                int remain = lim - (w << 5);
                unsigned valid = (remain >= 32) ? 0xFFFFFFFFu : ((1u << remain) - 1u);
                unsigned rw = M[((w << 5) + lane) * MWORDS + w];
                unsigned cur = __shfl_sync(0xffffffffu, sup, w);
                unsigned rem = ~cur & valid;
                while (rem) {
                    int t = __ffs(rem) - 1;
                    int i = (w << 5) + t;
                    unsigned roww = __shfl_sync(0xffffffffu, rw, t);
                    if (lane < MWORDS) sup |= M[i * MWORDS + lane];
                    if (lane == 0) kept_idx[nk] = (short)i;
                    nk++;
                    if (nk >= MAX_OUT) { rem = 0; break; }
                    rem &= ~(roww | (1u << t));
                }
                if (nk >= MAX_OUT) break;
            }
            if (lane == 0) sh_nk = nk;
        }
        __syncthreads();
        nk_fast = sh_nk;

        if (nk_fast >= MAX_OUT) {
            // common case: done — zero coarse hist (never read) and output
            for (int i = tid; i < NBINS; i += 1024) gh[i] = 0u;
            if (tid < MAX_OUT) {
                int k0 = tid;
                int i = kept_idx[k0];
                float4 bbv = scand[i];
                out5[k0 * 5 + 0] = bbv.x;
                out5[k0 * 5 + 1] = bbv.y;
                out5[k0 * 5 + 2] = bbv.z;
                out5[k0 * 5 + 3] = bbv.w;
                out5[k0 * 5 + 4] = __uint_as_float((unsigned int)(fcand[i] >> 32));
                if (write_cats) ocat[k0] = (float)cls8[i];
            }
            return;
        }
    }

    // ================= LAZY coarse walk (rare) =================
    if (warp == 0) {
        unsigned run = 0;
        int foundf = 0, founds = 0;
        unsigned Tbf = 0, fcv = 0, Tb = 0, scv = 0;
        for (int c = 0; c < WALKCH; c++) {
            int bin = NBINS - 1 - c * 32 - lane;
            unsigned v = gh[bin];
            unsigned p = v;
            #pragma unroll
            for (int off = 1; off < 32; off <<= 1) {
                unsigned t = __shfl_up_sync(0xffffffffu, p, off);
                if (lane >= off) p += t;
            }
            unsigned cum = run + p;
            if (!foundf) {
                unsigned cr = __ballot_sync(0xffffffffu, cum >= FKTGT && cum - v < FKTGT);
                if (cr) {
                    int src = __ffs(cr) - 1;
                    Tbf = __shfl_sync(0xffffffffu, (unsigned)bin, src);
                    fcv = __shfl_sync(0xffffffffu, cum, src);
                    foundf = 1;
                }
            }
            if (!founds) {
                unsigned cr = __ballot_sync(0xffffffffu, cum >= PRE_K && cum - v < PRE_K);
                if (cr) {
                    int src = __ffs(cr) - 1;
                    Tb  = __shfl_sync(0xffffffffu, (unsigned)bin, src);
                    scv = __shfl_sync(0xffffffffu, cum, src);
                    founds = 1;
                }
            }
            run = __shfl_sync(0xffffffffu, cum, 31);
            if (founds) break;
        }
        if (!foundf) { Tbf = 0; fcv = run; }
        if (!founds) { Tb = 0;  scv = run; }
        if (lane == 0) { s_Tb = Tb; s_Tbf = Tbf; s_scnt = scv; s_fcnt = fcv; }
    }
    __syncthreads();
    for (int i = tid; i < NBINS; i += 1024) gh[i] = 0u;   // zero after reads

    const unsigned int Tsb = (s_Tb + BINBASE) << 12;
    const unsigned int scnt = s_scnt;

    if (fine_ok) {
        // fine path ran but nk < MAX_OUT: complete iff we scanned everything
        if ((int)cnt <= MROWS && cnt >= scnt) {
            if (tid < MAX_OUT) {
                int k0 = tid;
                float vx1 = 0, vy1 = 0, vx2 = 0, vy2 = 0, vs = 0, vc = 0;
                if (k0 < nk_fast) {
                    int i = kept_idx[k0];
                    float4 bbv = scand[i];
                    vx1 = bbv.x; vy1 = bbv.y; vx2 = bbv.z; vy2 = bbv.w;
                    vs  = __uint_as_float((unsigned int)(fcand[i] >> 32));
                    vc  = (float)cls8[i];
                }
                out5[k0 * 5 + 0] = vx1;
                out5[k0 * 5 + 1] = vy1;
                out5[k0 * 5 + 2] = vx2;
                out5[k0 * 5 + 3] = vy2;
                out5[k0 * 5 + 4] = vs;
                if (write_cats) ocat[k0] = vc;
            }
            return;
        }
    } else if (s_fcnt <= FCAP) {
        // ================= COARSE FAST PATH (u64 sweep of g_keys) ===========
        if (tid == 0) s_fc = 0;
        __syncthreads();
        const unsigned Tf = (s_Tbf + BINBASE) << 12;
        #pragma unroll
        for (int it = 0; it < 8; it++) {
            unsigned long long kk[4];
            #pragma unroll
            for (int u = 0; u < 4; u++) kk[u] = keys[it * 4096 + u * 1024 + tid];
            #pragma unroll
            for (int u = 0; u < 4; u++) {
                unsigned int sb = (unsigned int)(kk[u] >> 32);
                bool cf = (sb >= Tf);
                unsigned balf = __ballot_sync(0xffffffffu, cf);
                if (balf) {
                    int leader = __ffs(balf) - 1;
                    unsigned int basep = 0;
                    if (lane == leader) basep = atomicAdd(&s_fc, (unsigned)__popc(balf));
                    basep = __shfl_sync(0xffffffffu, basep, leader);
                    if (cf) {
                        unsigned int pos = basep + (unsigned)__popc(balf & ((1u << lane) - 1u));
                        if (pos < FCAP) fcand[pos] = kk[u];
                    }
                }
            }
        }
        __syncthreads();
        cnt = s_fc; if (cnt > FCAP) cnt = FCAP;

        int nsort = 64;
        while (nsort < (int)cnt) nsort <<= 1;
        if (tid < nsort && tid >= (int)cnt) fcand[tid] = 0ULL;
        __syncthreads();
        if (tid < nsort) {
            unsigned long long v = fcand[tid];
            #pragma unroll
            for (int k = 2; k <= 32; k <<= 1) {
                #pragma unroll
                for (int j = k >> 1; j >= 1; j >>= 1) {
                    unsigned long long o = __shfl_xor_sync(0xffffffffu, v, j);
                    bool up    = ((tid & k) == 0);
                    bool lower = ((tid & j) == 0);
                    unsigned long long mx = v > o ? v : o;
                    unsigned long long mn = v > o ? o : v;
                    v = (up == lower) ? mx : mn;
                }
            }
            fcand[tid] = v;
        }
        __syncthreads();
        for (int k = 64; k <= nsort; k <<= 1) {
            for (int j = k >> 1; j >= 32; j >>= 1) {
                if (tid < nsort) {
                    int l = tid ^ j;
                    if (l > tid) {
                        unsigned long long a = fcand[tid], bb = fcand[l];
                        bool up = ((tid & k) == 0);
                        if ((a < bb) == up) { fcand[tid] = bb; fcand[l] = a; }
                    }
                }
                __syncthreads();
            }
            if (tid < nsort) {
                unsigned long long v = fcand[tid];
                #pragma unroll
                for (int j = 16; j >= 1; j >>= 1) {
                    unsigned long long o = __shfl_xor_sync(0xffffffffu, v, j);
                    bool up    = ((tid & k) == 0);
                    bool lower = ((tid & j) == 0);
                    unsigned long long mx = v > o ? v : o;
                    unsigned long long mn = v > o ? o : v;
                    v = (up == lower) ? mx : mn;
                }
                fcand[tid] = v;
            }
            __syncthreads();
        }

        {
            unsigned long long k = (tid < (int)cnt) ? fcand[tid] : 0ULL;
            if (k == 0ULL) {
                cls8[tid] = 0xFF;
                scand[tid] = make_float4(0.f, 0.f, 0.f, 0.f);
            } else {
                int idx = (NB - 1) - (int)(unsigned int)k;
                scand[tid] = *(const float4*)(bxs + (size_t)idx * 4);
                cls8[tid]  = cats[idx];
            }
        }
        #pragma unroll
        for (int u = tid; u < MROWS * MWORDS; u += 1024) M[u] = 0u;
        if (tid < NCLS) cpos[tid] = 0u;
        __syncthreads();

        const int lim = ((int)cnt < MROWS) ? (int)cnt : MROWS;

        if (tid < lim) atomicAdd(&cpos[cls8[tid]], 1u);
        __syncthreads();
        if (warp == 0) {
            unsigned carry = 0;
            if (lane == 0) coff[0] = 0;
            #pragma unroll
            for (int c0 = 0; c0 < NCLS; c0 += 32) {
                int idx = c0 + lane;
                unsigned v = (idx < NCLS) ? cpos[idx] : 0u;
                unsigned p = v;
                #pragma unroll
                for (int off = 1; off < 32; off <<= 1) {
                    unsigned t = __shfl_up_sync(0xffffffffu, p, off);
                    if (lane >= off) p += t;
                }
                if (idx < NCLS) coff[idx + 1] = (unsigned short)(carry + p);
                carry += __shfl_sync(0xffffffffu, p, 31);
            }
        }
        __syncthreads();
        if (tid < NCLS) cpos[tid] = coff[tid];
        __syncthreads();
        if (tid < lim) {
            unsigned p = atomicAdd(&cpos[cls8[tid]], 1u);
            clist[p] = (unsigned short)tid;
        }
        __syncthreads();

        if (tid < lim) {
            const int r = tid;
            const int c = cls8[r];
            float4 br = scand[r];
            float arr = fmaxf(br.z - br.x, 0.f) * fmaxf(br.w - br.y, 0.f);
            const int e0 = coff[c], e1 = coff[c + 1];
            for (int e = e0; e < e1; e++) {
                int j = clist[e];
                if (j == r) continue;
                float4 bj = scand[j];
                float ix1 = fmaxf(br.x, bj.x);
                float iy1 = fmaxf(br.y, bj.y);
                float ix2 = fminf(br.z, bj.z);
                float iy2 = fminf(br.w, bj.w);
                float inter = fmaxf(ix2 - ix1, 0.f) * fmaxf(iy2 - iy1, 0.f);
                float aj = fmaxf(bj.z - bj.x, 0.f) * fmaxf(bj.w - bj.y, 0.f);
                float uni = arr + aj - inter;
                if (inter / fmaxf(uni, 1e-9f) > 0.5f)
                    atomicOr(&M[r * MWORDS + (j >> 5)], 1u << (j & 31));
            }
        }
        __syncthreads();

        if (tid < 32) {
            unsigned sup = 0;
            int nk = 0;
            const int nwords = (lim + 31) >> 5;
            for (int w = 0; w < nwords; w++) {
                int remain = lim - (w << 5);
                unsigned valid = (remain >= 32) ? 0xFFFFFFFFu : ((1u << remain) - 1u);
                unsigned rw = M[((w << 5) + lane) * MWORDS + w];
                unsigned cur = __shfl_sync(0xffffffffu, sup, w);
                unsigned rem = ~cur & valid;
                while (rem) {
                    int t = __ffs(rem) - 1;
                    int i = (w << 5) + t;
                    unsigned roww = __shfl_sync(0xffffffffu, rw, t);
                    if (lane < MWORDS) sup |= M[i * MWORDS + lane];
                    if (lane == 0) kept_idx[nk] = (short)i;
                    nk++;
                    if (nk >= MAX_OUT) { rem = 0; break; }
                    rem &= ~(roww | (1u << t));
                }
                if (nk >= MAX_OUT) break;
            }
            if (lane == 0) sh_nk = nk;
        }
        __syncthreads();

        const int nk = sh_nk;
        bool complete = (nk >= MAX_OUT) || ((int)cnt <= MROWS && cnt >= scnt);
        if (complete) {
            if (tid < MAX_OUT) {
                int k0 = tid;
                float vx1 = 0, vy1 = 0, vx2 = 0, vy2 = 0, vs = 0, vc = 0;
                if (k0 < nk) {
                    int i = kept_idx[k0];
                    float4 bbv = scand[i];
                    vx1 = bbv.x; vy1 = bbv.y; vx2 = bbv.z; vy2 = bbv.w;
                    vs  = __uint_as_float((unsigned int)(fcand[i] >> 32));
                    vc  = (float)cls8[i];
                }
                out5[k0 * 5 + 0] = vx1;
                out5[k0 * 5 + 1] = vy1;
                out5[k0 * 5 + 2] = vx2;
                out5[k0 * 5 + 3] = vy2;
                out5[k0 * 5 + 4] = vs;
                if (write_cats) ocat[k0] = vc;
            }
            return;
        }
    }

    // ================= FULL PATH (inline fallback) =================
    if (tid == 0) s_cnt2 = 0;
    __syncthreads();

    #pragma unroll
    for (int it = 0; it < 8; it++) {
        unsigned long long kk[4];
        #pragma unroll
        for (int u = 0; u < 4; u++) kk[u] = keys[it * 4096 + u * 1024 + tid];
        #pragma unroll
        for (int u = 0; u < 4; u++) {
            unsigned int sb = (unsigned int)(kk[u] >> 32);
            bool c = (sb >= Tsb);
            unsigned bal = __ballot_sync(0xffffffffu, c);
            if (bal) {
                int leader = __ffs(bal) - 1;
                unsigned int basep = 0;
                if (lane == leader) basep = atomicAdd(&s_cnt2, (unsigned)__popc(bal));
                basep = __shfl_sync(0xffffffffu, basep, leader);
                if (c) {
                    unsigned int pos = basep + (unsigned)__popc(bal & ((1u << lane) - 1u));
                    if (pos < CAP) cand[pos] = kk[u];
                }
            }
        }
    }
    __syncthreads();
    unsigned int cnt2 = s_cnt2; if (cnt2 > CAP) cnt2 = CAP;
    #pragma unroll
    for (int s = 0; s < 4; s++) {
        int i = s * 1024 + tid;
        if (i >= (int)cnt2) cand[i] = 0ULL;
    }
    __syncthreads();

    {
        unsigned long long v[4];
        #pragma unroll
        for (int s = 0; s < 4; s++) v[s] = cand[s * 1024 + tid];
        #pragma unroll
        for (int k = 2; k <= 32; k <<= 1) {
            #pragma unroll
            for (int j = k >> 1; j >= 1; j >>= 1) {
                #pragma unroll
                for (int s = 0; s < 4; s++) {
                    int i = s * 1024 + tid;
                    unsigned long long o = __shfl_xor_sync(0xffffffffu, v[s], j);
                    bool up    = ((i & k) == 0);
                    bool lower = ((i & j) == 0);
                    unsigned long long mx = v[s] > o ? v[s] : o;
                    unsigned long long mn = v[s] > o ? o : v[s];
                    v[s] = (up == lower) ? mx : mn;
                }
            }
        }
        #pragma unroll
        for (int s = 0; s < 4; s++) cand[s * 1024 + tid] = v[s];
    }
    __syncthreads();
    for (int k = 64; k <= CAP; k <<= 1) {
        for (int j = k >> 1; j >= 32; j >>= 1) {
            #pragma unroll
            for (int s0 = 0; s0 < CAP; s0 += 1024) {
                int i = s0 + tid;
                int l = i ^ j;
                if (l > i) {
                    unsigned long long a = cand[i], bb = cand[l];
                    bool up = ((i & k) == 0);
                    if ((a < bb) == up) { cand[i] = bb; cand[l] = a; }
                }
            }
            __syncthreads();
        }
        {
            unsigned long long v[4];
            #pragma unroll
            for (int s = 0; s < 4; s++) v[s] = cand[s * 1024 + tid];
            #pragma unroll
            for (int j = 16; j >= 1; j >>= 1) {
                #pragma unroll
                for (int s = 0; s < 4; s++) {
                    int i = s * 1024 + tid;
                    unsigned long long o = __shfl_xor_sync(0xffffffffu, v[s], j);
                    bool up    = ((i & k) == 0);
                    bool lower = ((i & j) == 0);
                    unsigned long long mx = v[s] > o ? v[s] : o;
                    unsigned long long mn = v[s] > o ? o : v[s];
                    v[s] = (up == lower) ? mx : mn;
                }
            }
            #pragma unroll
            for (int s = 0; s < 4; s++) cand[s * 1024 + tid] = v[s];
        }
        __syncthreads();
    }

    for (int i = tid; i < PRE_K; i += 1024) {
        unsigned long long k = cand[i];
        if (k == 0ULL) {
            scls2[i] = -1;
            scand2[i] = make_float4(0.f, 0.f, 0.f, 0.f);
        } else {
            int idx = (NB - 1) - (int)(unsigned int)k;
            scand2[i] = *(const float4*)(bxs + (size_t)idx * 4);
            scls2[i]  = (short)cats[idx];
        }
    }
    __syncthreads();

    if (tid < 32) {
        int nk = run_nms_warp(scand2, scls2, kept_idx, PRE_K, lane);
        if (lane == 0) sh_nk = nk;
    }
    __syncthreads();

    const int nk = sh_nk;
    for (int k0 = tid; k0 < MAX_OUT; k0 += 1024) {
        float vx1 = 0, vy1 = 0, vx2 = 0, vy2 = 0, vs = 0, vc = 0;
        if (k0 < nk) {
            int i = kept_idx[k0];
            float4 bbv = scand2[i];
            vx1 = bbv.x; vy1 = bbv.y; vx2 = bbv.z; vy2 = bbv.w;
            vs  = __uint_as_float((unsigned int)(cand[i] >> 32));
            vc  = (float)scls2[i];
        }
        out5[k0 * 5 + 0] = vx1;
        out5[k0 * 5 + 1] = vy1;
        out5[k0 * 5 + 2] = vx2;
        out5[k0 * 5 + 3] = vy2;
        out5[k0 * 5 + 4] = vs;
        if (write_cats) ocat[k0] = vc;
    }
}

// ---------------- launch ----------------------------------------------------
extern "C" void kernel_launch(void* const* d_in, const int* in_sizes, int n_in,
                              void* d_out, int out_size) {
    const float* boxes = (const float*)d_in[0];
    const float* confs = (const float*)d_in[1];
    if (n_in >= 2 && in_sizes[0] > in_sizes[1]) {
        boxes = (const float*)d_in[1];
        confs = (const float*)d_in[0];
    }
    float* out = (float*)d_out;

    if (out_size != BATCHES * MAX_OUT * 6)
        cudaMemsetAsync(d_out, 0, (size_t)out_size * sizeof(float), 0);

    cudaFuncSetAttribute(score_kernel,
                         cudaFuncAttributeMaxDynamicSharedMemorySize, SCORE_DYN);
    score_kernel<<<(BATCHES * NB) / (SB_ANCH * NTILES), SB_ANCH, SCORE_DYN>>>(confs);

    int write_cats = (out_size >= BATCHES * MAX_OUT * 6) ? 1 : 0;
    cudaFuncSetAttribute(fused_kernel,
                         cudaFuncAttributeMaxDynamicSharedMemorySize, FUSED_DYN);
    fused_kernel<<<BATCHES, 1024, FUSED_DYN>>>(boxes, out, write_cats);
}